// round 14
// baseline (speedup 1.0000x reference)
#include <cuda_runtime.h>
#include <cuda_bf16.h>

#define NW 8192
#define NS 8192
#define FD 1024
#define EMB 128
#define QN 1024
#define NC 80
#define POSCAP 512

// ---------------- scratch (device globals; no allocation) ----------------
__device__ float g_q[NW * EMB];          // weak encodings
__device__ float g_k[NS * EMB];          // strong encodings
__device__ int   g_rank[NW];
__device__ int   g_posS[NC * POSCAP];
__device__ int   g_histS[NC];
__device__ float g_m[2 * NW];            // per-half running max
__device__ float g_l[2 * NW];            // per-half running sumexp
__device__ float g_psum[1024];
__device__ float g_pcnt[1024];
__device__ unsigned g_ticket;

// ---------------- helpers ----------------
__device__ __forceinline__ uint2 f4bf(float4 v) {
    __nv_bfloat162 lo = __floats2bfloat162_rn(v.x, v.y);
    __nv_bfloat162 hi = __floats2bfloat162_rn(v.z, v.w);
    uint2 r;
    r.x = *reinterpret_cast<unsigned int*>(&lo);
    r.y = *reinterpret_cast<unsigned int*>(&hi);
    return r;
}

__device__ __forceinline__ void ldsm4(unsigned &r0, unsigned &r1, unsigned &r2, unsigned &r3, unsigned addr) {
    asm volatile("ldmatrix.sync.aligned.m8n8.x4.shared.b16 {%0,%1,%2,%3}, [%4];"
                 : "=r"(r0), "=r"(r1), "=r"(r2), "=r"(r3) : "r"(addr));
}
__device__ __forceinline__ void ldsm4t(unsigned &r0, unsigned &r1, unsigned &r2, unsigned &r3, unsigned addr) {
    asm volatile("ldmatrix.sync.aligned.m8n8.x4.trans.shared.b16 {%0,%1,%2,%3}, [%4];"
                 : "=r"(r0), "=r"(r1), "=r"(r2), "=r"(r3) : "r"(addr));
}
__device__ __forceinline__ void mma16816(float* c, const unsigned* a, unsigned b0, unsigned b1) {
    asm volatile("mma.sync.aligned.m16n8k16.row.col.f32.bf16.bf16.f32 "
                 "{%0,%1,%2,%3}, {%4,%5,%6,%7}, {%8,%9}, {%0,%1,%2,%3};"
                 : "+f"(c[0]), "+f"(c[1]), "+f"(c[2]), "+f"(c[3])
                 : "r"(a[0]), "r"(a[1]), "r"(a[2]), "r"(a[3]), "r"(b0), "r"(b1));
}

// ---------------- label logic (v3: smem-staged, one global burst) ----------
// blocks [0,80): strong labels -> posS/histS ; blocks [80,160): weak -> rank.
__global__ void label_scan_kernel(const int* __restrict__ slab,
                                  const int* __restrict__ wlab) {
    const int b = blockIdx.x;
    const bool strong = b < NC;
    const int c = strong ? b : b - NC;
    const int* lab = strong ? slab : wlab;
    __shared__ int sl[NS];          // 32 KB
    __shared__ int wsum[8];
    const int tid = threadIdx.x, lane = tid & 31, wid = tid >> 5;
    if (b == 0 && tid == 0) g_ticket = 0;   // reset for row_ce last-block pattern

#pragma unroll
    for (int it = 0; it < 8; it++) {
        int lin = it * 256 + tid;
        int4 v = reinterpret_cast<const int4*>(lab)[lin];
        *reinterpret_cast<int4*>(&sl[lin * 4]) = v;
    }
    __syncthreads();

    const int base = tid * 32;
    int cnt = 0;
#pragma unroll
    for (int j = 0; j < 32; j++) cnt += (sl[base + j] == c) ? 1 : 0;

    int x = cnt;
#pragma unroll
    for (int o = 1; o < 32; o <<= 1) {
        int y = __shfl_up_sync(0xffffffffu, x, o);
        if (lane >= o) x += y;
    }
    if (lane == 31) wsum[wid] = x;
    __syncthreads();
    int wpre = 0, tot = 0;
#pragma unroll
    for (int ww = 0; ww < 8; ww++) {
        if (ww < wid) wpre += wsum[ww];
        tot += wsum[ww];
    }
    int pos = wpre + x - cnt;

#pragma unroll
    for (int j = 0; j < 32; j++) {
        int jj = base + j;
        if (sl[jj] == c) {
            if (strong) { if (pos < POSCAP) g_posS[c * POSCAP + pos] = jj; }
            else g_rank[jj] = pos;
            pos++;
        }
    }
    if (strong && tid == 0) g_histS[c] = tot;
}

// ---------------- fused dual encoder GEMM (BM=64, 2 CTAs/SM) ---------------
__device__ __forceinline__ void enc_load(const float* __restrict__ A, const float* __restrict__ B,
                                         int m0, int kt, int tid, float4* ra, float4* rb) {
    const float* Ap = A + m0 * FD + kt * 32;
    const float* Bp = B + kt * 32 * EMB;
#pragma unroll
    for (int it = 0; it < 2; it++) {
        int lin = it * 256 + tid;
        ra[it] = *reinterpret_cast<const float4*>(Ap + (lin >> 3) * FD + (lin & 7) * 4);
    }
#pragma unroll
    for (int it = 0; it < 4; it++) {
        int lin = it * 256 + tid;
        rb[it] = *reinterpret_cast<const float4*>(Bp + (lin >> 5) * EMB + (lin & 31) * 4);
    }
}
__device__ __forceinline__ void enc_sts(__nv_bfloat16 (*sA)[40], __nv_bfloat16 (*sB)[136],
                                        int tid, const float4* ra, const float4* rb) {
#pragma unroll
    for (int it = 0; it < 2; it++) {
        int lin = it * 256 + tid;
        *reinterpret_cast<uint2*>(&sA[lin >> 3][(lin & 7) * 4]) = f4bf(ra[it]);
    }
#pragma unroll
    for (int it = 0; it < 4; it++) {
        int lin = it * 256 + tid;
        *reinterpret_cast<uint2*>(&sB[lin >> 5][(lin & 31) * 4]) = f4bf(rb[it]);
    }
}

__global__ __launch_bounds__(256, 2) void encoder_gemm_kernel(
    const float* __restrict__ fw, const float* __restrict__ fs,
    const float* __restrict__ Wq, const float* __restrict__ bq,
    const float* __restrict__ Wk, const float* __restrict__ bk) {
    __shared__ __align__(16) __nv_bfloat16 sA[2][64][40];    // 80B row stride
    __shared__ __align__(16) __nv_bfloat16 sB[2][32][136];   // 272B row stride
    const int tid = threadIdx.x, lane = tid & 31, wid = tid >> 5;
    const int wm = wid >> 2, wn = wid & 3;   // 2 x 4 warps over 64 x 128
    const float *A, *B, *bias;
    float* C;
    if (blockIdx.x < 128) { A = fw; B = Wq; bias = bq; C = g_q; }
    else                  { A = fs; B = Wk; bias = bk; C = g_k; }
    const int m0 = (blockIdx.x & 127) * 64;

    float acc[2][4][4];
#pragma unroll
    for (int mt = 0; mt < 2; mt++)
#pragma unroll
        for (int nt = 0; nt < 4; nt++)
#pragma unroll
            for (int j = 0; j < 4; j++) acc[mt][nt][j] = 0.f;

    float4 ra[2], rb[4];
    enc_load(A, B, m0, 0, tid, ra, rb);
    enc_sts(sA[0], sB[0], tid, ra, rb);
    __syncthreads();

    for (int kt = 0; kt < FD / 32; kt++) {
        const int buf = kt & 1;
        if (kt < FD / 32 - 1) enc_load(A, B, m0, kt + 1, tid, ra, rb);
        unsigned abase = (unsigned)__cvta_generic_to_shared(&sA[buf][0][0]);
        unsigned bbase = (unsigned)__cvta_generic_to_shared(&sB[buf][0][0]);
#pragma unroll
        for (int ks = 0; ks < 2; ks++) {
            unsigned af[2][4], bfr[2][4];
#pragma unroll
            for (int mt = 0; mt < 2; mt++) {
                int row = wm * 32 + mt * 16 + (lane & 15);
                int col = ks * 16 + (lane >> 4) * 8;
                ldsm4(af[mt][0], af[mt][1], af[mt][2], af[mt][3],
                      abase + (unsigned)(row * 40 + col) * 2u);
            }
#pragma unroll
            for (int p = 0; p < 2; p++) {
                int qd = lane >> 3;
                int row = ks * 16 + (qd & 1) * 8 + (lane & 7);
                int col = wn * 32 + p * 16 + (qd >> 1) * 8;
                ldsm4t(bfr[p][0], bfr[p][1], bfr[p][2], bfr[p][3],
                       bbase + (unsigned)(row * 136 + col) * 2u);
            }
#pragma unroll
            for (int nt = 0; nt < 4; nt++) {
                unsigned b0 = bfr[nt >> 1][(nt & 1) * 2], b1 = bfr[nt >> 1][(nt & 1) * 2 + 1];
                mma16816(acc[0][nt], af[0], b0, b1);
                mma16816(acc[1][nt], af[1], b0, b1);
            }
        }
        if (kt < FD / 32 - 1) enc_sts(sA[buf ^ 1], sB[buf ^ 1], tid, ra, rb);
        __syncthreads();
    }
    const int g = lane >> 2, qd2 = (lane & 3) * 2;
#pragma unroll
    for (int mt = 0; mt < 2; mt++) {
        int r0 = m0 + wm * 32 + mt * 16 + g;
#pragma unroll
        for (int nt = 0; nt < 4; nt++) {
            int c = wn * 32 + nt * 8 + qd2;
            float bx = bias[c], by = bias[c + 1];
            float2 v0 = make_float2(acc[mt][nt][0] + bx, acc[mt][nt][1] + by);
            float2 v1 = make_float2(acc[mt][nt][2] + bx, acc[mt][nt][3] + by);
            *reinterpret_cast<float2*>(&C[r0 * EMB + c]) = v0;
            *reinterpret_cast<float2*>(&C[(r0 + 8) * EMB + c]) = v1;
        }
    }
}

// ---------------- logits GEMM + streaming logsumexp (single-buf, 2 CTA/SM) -
// grid 128: rowblk = bid>>1 (128 rows), half = bid&1 (512 cols -> 8 chunks of 64).
__global__ __launch_bounds__(256, 2) void logits_kernel(const float* __restrict__ queue) {
    __shared__ __align__(16) __nv_bfloat16 sB[128][72];   // 144B row stride, 18.4KB
    const int tid = threadIdx.x, lane = tid & 31, w = tid >> 5;
    const int m0 = (blockIdx.x >> 1) * 128, n0 = (blockIdx.x & 1) * 512;
    unsigned base0 = (unsigned)__cvta_generic_to_shared(&sB[0][0]);

    // extract A fragments in two passes through sB (k-cols 0:64 then 64:128)
    unsigned af[8][4];
#pragma unroll
    for (int s = 0; s < 2; s++) {
        if (s == 1) __syncthreads();
#pragma unroll
        for (int it = 0; it < 8; it++) {
            int lin = it * 256 + tid;
            int row = lin >> 4, c4 = (lin & 15) * 4;
            float4 v = *reinterpret_cast<const float4*>(g_q + (m0 + row) * EMB + s * 64 + c4);
            *reinterpret_cast<uint2*>(&sB[row][c4]) = f4bf(v);
        }
        __syncthreads();
#pragma unroll
        for (int k = 0; k < 4; k++) {
            int row = w * 16 + (lane & 15);
            int col = k * 16 + (lane >> 4) * 8;
            ldsm4(af[s * 4 + k][0], af[s * 4 + k][1], af[s * 4 + k][2], af[s * 4 + k][3],
                  base0 + (unsigned)(row * 72 + col) * 2u);
        }
    }

    float m0r = -1e30f, m1r = -1e30f, l0r = 0.f, l1r = 0.f;
    for (int ch = 0; ch < 8; ch++) {
        __syncthreads();   // all reads of sB done (af for ch=0, bfr for ch>0)
#pragma unroll
        for (int it = 0; it < 8; it++) {
            int lin = it * 256 + tid;
            float4 v = *reinterpret_cast<const float4*>(
                queue + (lin >> 4) * QN + n0 + ch * 64 + (lin & 15) * 4);
            *reinterpret_cast<uint2*>(&sB[lin >> 4][(lin & 15) * 4]) = f4bf(v);
        }
        __syncthreads();
        float acc[8][4];
#pragma unroll
        for (int nt = 0; nt < 8; nt++) { acc[nt][0] = acc[nt][1] = acc[nt][2] = acc[nt][3] = 0.f; }
#pragma unroll
        for (int ks = 0; ks < 8; ks++) {
            unsigned bfr[4][4];
#pragma unroll
            for (int p = 0; p < 4; p++) {
                int qd = lane >> 3;
                int row = ks * 16 + (qd & 1) * 8 + (lane & 7);
                int col = p * 16 + (qd >> 1) * 8;
                ldsm4t(bfr[p][0], bfr[p][1], bfr[p][2], bfr[p][3],
                       base0 + (unsigned)(row * 72 + col) * 2u);
            }
#pragma unroll
            for (int nt = 0; nt < 8; nt++)
                mma16816(acc[nt], af[ks], bfr[nt >> 1][(nt & 1) * 2], bfr[nt >> 1][(nt & 1) * 2 + 1]);
        }
        float c0 = -1e30f, c1 = -1e30f;
#pragma unroll
        for (int nt = 0; nt < 8; nt++) {
            c0 = fmaxf(c0, fmaxf(acc[nt][0], acc[nt][1]));
            c1 = fmaxf(c1, fmaxf(acc[nt][2], acc[nt][3]));
        }
        c0 = fmaxf(c0, __shfl_xor_sync(0xffffffffu, c0, 1));
        c0 = fmaxf(c0, __shfl_xor_sync(0xffffffffu, c0, 2));
        c1 = fmaxf(c1, __shfl_xor_sync(0xffffffffu, c1, 1));
        c1 = fmaxf(c1, __shfl_xor_sync(0xffffffffu, c1, 2));
        float n0m = fmaxf(m0r, c0), n1m = fmaxf(m1r, c1);
        float s0 = 0.f, s1 = 0.f;
#pragma unroll
        for (int nt = 0; nt < 8; nt++) {
            s0 += __expf(acc[nt][0] - n0m) + __expf(acc[nt][1] - n0m);
            s1 += __expf(acc[nt][2] - n1m) + __expf(acc[nt][3] - n1m);
        }
        s0 += __shfl_xor_sync(0xffffffffu, s0, 1);
        s0 += __shfl_xor_sync(0xffffffffu, s0, 2);
        s1 += __shfl_xor_sync(0xffffffffu, s1, 1);
        s1 += __shfl_xor_sync(0xffffffffu, s1, 2);
        l0r = l0r * __expf(m0r - n0m) + s0; m0r = n0m;
        l1r = l1r * __expf(m1r - n1m) + s1; m1r = n1m;
    }
    if ((lane & 3) == 0) {
        int half = blockIdx.x & 1;
        int r = m0 + w * 16 + (lane >> 2);
        g_m[half * NW + r] = m0r;      g_l[half * NW + r] = l0r;
        g_m[half * NW + r + 8] = m1r;  g_l[half * NW + r + 8] = l1r;
    }
}

// ---------------- per-row CE v3: one row per warp + fused final ------------
// grid 1024 x 8 warps = 8192 warps, one row each: single idx-chain per warp,
// fully overlapped across resident warps; dot is lane-parallel/coalesced.
__global__ void row_ce_kernel(const int* __restrict__ wlab, float* __restrict__ out) {
    const int tid = threadIdx.x, lane = tid & 31, wid = tid >> 5;
    __shared__ float rs[8], rc[8];
    __shared__ int slast;

    const int i = blockIdx.x * 8 + wid;
    // idx chain (uniform across warp; broadcast loads)
    int c = wlab[i];
    int inrange = (c >= 0 && c < NC) ? 1 : 0;
    int cc = inrange ? c : 0;
    int cnt = g_histS[cc];
    int valid = (inrange && cnt > 0) ? 1 : 0;
    int sel = g_rank[i] % (cnt > 0 ? cnt : 1);
    if (sel >= POSCAP || sel < 0) sel = 0;
    int idx = valid ? g_posS[cc * POSCAP + sel] : 0;

    // coalesced per-row dot: lane j covers elements 4j..4j+3
    float4 a = *reinterpret_cast<const float4*>(g_q + i * EMB + lane * 4);
    float4 b = *reinterpret_cast<const float4*>(g_k + idx * EMB + lane * 4);
    float s = a.x * b.x + a.y * b.y + a.z * b.z + a.w * b.w;
#pragma unroll
    for (int o = 16; o; o >>= 1) s += __shfl_xor_sync(0xffffffffu, s, o);

    float ma = g_m[i], la = g_l[i], mb = g_m[NW + i], lb = g_l[NW + i];
    float M = fmaxf(ma, mb);
    float L = la * __expf(ma - M) + lb * __expf(mb - M);
    float lpos = s;
    float Mf = fmaxf(M, lpos);
    float Lf = L * __expf(M - Mf) + __expf(lpos - Mf);
    float ce = Mf + logf(Lf) - lpos;
    if (lane == 0) {
        rs[wid] = ce * (valid ? 1.f : 0.f);
        rc[wid] = valid ? 1.f : 0.f;
    }
    __syncthreads();
    if (tid == 0) {
        float A = 0.f, C = 0.f;
#pragma unroll
        for (int ww = 0; ww < 8; ww++) { A += rs[ww]; C += rc[ww]; }
        g_psum[blockIdx.x] = A;
        g_pcnt[blockIdx.x] = C;
        __threadfence();
        unsigned t = atomicAdd(&g_ticket, 1u);
        slast = (t == 1023u) ? 1 : 0;
    }
    __syncthreads();
    // last block: deterministic fixed-order reduction over 1024 partials
    if (slast) {
        float s2 = 0.f, c2 = 0.f;
#pragma unroll
        for (int k = 0; k < 4; k++) { s2 += g_psum[tid * 4 + k]; c2 += g_pcnt[tid * 4 + k]; }
#pragma unroll
        for (int o = 16; o; o >>= 1) {
            s2 += __shfl_xor_sync(0xffffffffu, s2, o);
            c2 += __shfl_xor_sync(0xffffffffu, c2, o);
        }
        __syncthreads();   // rs/rc reuse
        if (lane == 0) { rs[wid] = s2; rc[wid] = c2; }
        __syncthreads();
        if (tid == 0) {
            float S = 0.f, Cn = 0.f;
#pragma unroll
            for (int ww = 0; ww < 8; ww++) { S += rs[ww]; Cn += rc[ww]; }
            out[0] = S / fmaxf(Cn, 1.f);
        }
    }
}

// ---------------- launch ----------------
extern "C" void kernel_launch(void* const* d_in, const int* in_sizes, int n_in,
                              void* d_out, int out_size) {
    const float* fs    = (const float*)d_in[0];   // feats_strong [8192,1024]
    const float* fw    = (const float*)d_in[1];   // feats_weak   [8192,1024]
    const int*   slab  = (const int*)d_in[2];     // strong_labels (int32)
    const int*   wlab  = (const int*)d_in[3];     // weak_labels   (int32)
    const float* Wq    = (const float*)d_in[4];
    const float* bq    = (const float*)d_in[5];
    const float* Wk    = (const float*)d_in[6];
    const float* bk    = (const float*)d_in[7];
    const float* queue = (const float*)d_in[8];   // [1024,128] flat
    float* out = (float*)d_out;

    label_scan_kernel<<<2 * NC, 256>>>(slab, wlab);
    encoder_gemm_kernel<<<256, 256>>>(fw, fs, Wq, bq, Wk, bk);
    logits_kernel<<<128, 256>>>(queue);
    row_ce_kernel<<<1024, 256>>>(wlab, out);
}

// round 15
// speedup vs baseline: 1.0271x; 1.0271x over previous
#include <cuda_runtime.h>
#include <cuda_bf16.h>

#define NW 8192
#define NS 8192
#define FD 1024
#define EMB 128
#define QN 1024
#define NC 80
#define POSCAP 512

// ---------------- scratch (device globals; no allocation) ----------------
__device__ float g_q[NW * EMB];          // weak encodings
__device__ float g_k[NS * EMB];          // strong encodings
__device__ int   g_rank[NW];
__device__ int   g_posS[NC * POSCAP];
__device__ int   g_histS[NC];
__device__ float g_m[4 * NW];            // per-quarter running max
__device__ float g_l[4 * NW];            // per-quarter running sumexp
__device__ float g_psum[256];
__device__ float g_pcnt[256];
__device__ unsigned g_ticket;

// ---------------- helpers ----------------
__device__ __forceinline__ uint2 f4bf(float4 v) {
    __nv_bfloat162 lo = __floats2bfloat162_rn(v.x, v.y);
    __nv_bfloat162 hi = __floats2bfloat162_rn(v.z, v.w);
    uint2 r;
    r.x = *reinterpret_cast<unsigned int*>(&lo);
    r.y = *reinterpret_cast<unsigned int*>(&hi);
    return r;
}

__device__ __forceinline__ void ldsm4(unsigned &r0, unsigned &r1, unsigned &r2, unsigned &r3, unsigned addr) {
    asm volatile("ldmatrix.sync.aligned.m8n8.x4.shared.b16 {%0,%1,%2,%3}, [%4];"
                 : "=r"(r0), "=r"(r1), "=r"(r2), "=r"(r3) : "r"(addr));
}
__device__ __forceinline__ void ldsm4t(unsigned &r0, unsigned &r1, unsigned &r2, unsigned &r3, unsigned addr) {
    asm volatile("ldmatrix.sync.aligned.m8n8.x4.trans.shared.b16 {%0,%1,%2,%3}, [%4];"
                 : "=r"(r0), "=r"(r1), "=r"(r2), "=r"(r3) : "r"(addr));
}
__device__ __forceinline__ void mma16816(float* c, const unsigned* a, unsigned b0, unsigned b1) {
    asm volatile("mma.sync.aligned.m16n8k16.row.col.f32.bf16.bf16.f32 "
                 "{%0,%1,%2,%3}, {%4,%5,%6,%7}, {%8,%9}, {%0,%1,%2,%3};"
                 : "+f"(c[0]), "+f"(c[1]), "+f"(c[2]), "+f"(c[3])
                 : "r"(a[0]), "r"(a[1]), "r"(a[2]), "r"(a[3]), "r"(b0), "r"(b1));
}

// ---------------- label logic (v3: smem-staged, one global burst) ----------
// blocks [0,80): strong labels -> posS/histS ; blocks [80,160): weak -> rank.
__global__ void label_scan_kernel(const int* __restrict__ slab,
                                  const int* __restrict__ wlab) {
    const int b = blockIdx.x;
    const bool strong = b < NC;
    const int c = strong ? b : b - NC;
    const int* lab = strong ? slab : wlab;
    __shared__ int sl[NS];          // 32 KB
    __shared__ int wsum[8];
    const int tid = threadIdx.x, lane = tid & 31, wid = tid >> 5;
    if (b == 0 && tid == 0) g_ticket = 0;   // reset for row_ce last-block pattern

#pragma unroll
    for (int it = 0; it < 8; it++) {
        int lin = it * 256 + tid;
        int4 v = reinterpret_cast<const int4*>(lab)[lin];
        *reinterpret_cast<int4*>(&sl[lin * 4]) = v;
    }
    __syncthreads();

    const int base = tid * 32;
    int cnt = 0;
#pragma unroll
    for (int j = 0; j < 32; j++) cnt += (sl[base + j] == c) ? 1 : 0;

    int x = cnt;
#pragma unroll
    for (int o = 1; o < 32; o <<= 1) {
        int y = __shfl_up_sync(0xffffffffu, x, o);
        if (lane >= o) x += y;
    }
    if (lane == 31) wsum[wid] = x;
    __syncthreads();
    int wpre = 0, tot = 0;
#pragma unroll
    for (int ww = 0; ww < 8; ww++) {
        if (ww < wid) wpre += wsum[ww];
        tot += wsum[ww];
    }
    int pos = wpre + x - cnt;

#pragma unroll
    for (int j = 0; j < 32; j++) {
        int jj = base + j;
        if (sl[jj] == c) {
            if (strong) { if (pos < POSCAP) g_posS[c * POSCAP + pos] = jj; }
            else g_rank[jj] = pos;
            pos++;
        }
    }
    if (strong && tid == 0) g_histS[c] = tot;
}

// ---------------- fused dual encoder GEMM (BM=64, 2 CTAs/SM) ---------------
__device__ __forceinline__ void enc_load(const float* __restrict__ A, const float* __restrict__ B,
                                         int m0, int kt, int tid, float4* ra, float4* rb) {
    const float* Ap = A + m0 * FD + kt * 32;
    const float* Bp = B + kt * 32 * EMB;
#pragma unroll
    for (int it = 0; it < 2; it++) {
        int lin = it * 256 + tid;
        ra[it] = *reinterpret_cast<const float4*>(Ap + (lin >> 3) * FD + (lin & 7) * 4);
    }
#pragma unroll
    for (int it = 0; it < 4; it++) {
        int lin = it * 256 + tid;
        rb[it] = *reinterpret_cast<const float4*>(Bp + (lin >> 5) * EMB + (lin & 31) * 4);
    }
}
__device__ __forceinline__ void enc_sts(__nv_bfloat16 (*sA)[40], __nv_bfloat16 (*sB)[136],
                                        int tid, const float4* ra, const float4* rb) {
#pragma unroll
    for (int it = 0; it < 2; it++) {
        int lin = it * 256 + tid;
        *reinterpret_cast<uint2*>(&sA[lin >> 3][(lin & 7) * 4]) = f4bf(ra[it]);
    }
#pragma unroll
    for (int it = 0; it < 4; it++) {
        int lin = it * 256 + tid;
        *reinterpret_cast<uint2*>(&sB[lin >> 5][(lin & 31) * 4]) = f4bf(rb[it]);
    }
}

__global__ __launch_bounds__(256, 2) void encoder_gemm_kernel(
    const float* __restrict__ fw, const float* __restrict__ fs,
    const float* __restrict__ Wq, const float* __restrict__ bq,
    const float* __restrict__ Wk, const float* __restrict__ bk) {
    __shared__ __align__(16) __nv_bfloat16 sA[2][64][40];    // 80B row stride
    __shared__ __align__(16) __nv_bfloat16 sB[2][32][136];   // 272B row stride
    const int tid = threadIdx.x, lane = tid & 31, wid = tid >> 5;
    const int wm = wid >> 2, wn = wid & 3;   // 2 x 4 warps over 64 x 128
    const float *A, *B, *bias;
    float* C;
    if (blockIdx.x < 128) { A = fw; B = Wq; bias = bq; C = g_q; }
    else                  { A = fs; B = Wk; bias = bk; C = g_k; }
    const int m0 = (blockIdx.x & 127) * 64;

    float acc[2][4][4];
#pragma unroll
    for (int mt = 0; mt < 2; mt++)
#pragma unroll
        for (int nt = 0; nt < 4; nt++)
#pragma unroll
            for (int j = 0; j < 4; j++) acc[mt][nt][j] = 0.f;

    float4 ra[2], rb[4];
    enc_load(A, B, m0, 0, tid, ra, rb);
    enc_sts(sA[0], sB[0], tid, ra, rb);
    __syncthreads();

    for (int kt = 0; kt < FD / 32; kt++) {
        const int buf = kt & 1;
        if (kt < FD / 32 - 1) enc_load(A, B, m0, kt + 1, tid, ra, rb);
        unsigned abase = (unsigned)__cvta_generic_to_shared(&sA[buf][0][0]);
        unsigned bbase = (unsigned)__cvta_generic_to_shared(&sB[buf][0][0]);
#pragma unroll
        for (int ks = 0; ks < 2; ks++) {
            unsigned af[2][4], bfr[2][4];
#pragma unroll
            for (int mt = 0; mt < 2; mt++) {
                int row = wm * 32 + mt * 16 + (lane & 15);
                int col = ks * 16 + (lane >> 4) * 8;
                ldsm4(af[mt][0], af[mt][1], af[mt][2], af[mt][3],
                      abase + (unsigned)(row * 40 + col) * 2u);
            }
#pragma unroll
            for (int p = 0; p < 2; p++) {
                int qd = lane >> 3;
                int row = ks * 16 + (qd & 1) * 8 + (lane & 7);
                int col = wn * 32 + p * 16 + (qd >> 1) * 8;
                ldsm4t(bfr[p][0], bfr[p][1], bfr[p][2], bfr[p][3],
                       bbase + (unsigned)(row * 136 + col) * 2u);
            }
#pragma unroll
            for (int nt = 0; nt < 4; nt++) {
                unsigned b0 = bfr[nt >> 1][(nt & 1) * 2], b1 = bfr[nt >> 1][(nt & 1) * 2 + 1];
                mma16816(acc[0][nt], af[0], b0, b1);
                mma16816(acc[1][nt], af[1], b0, b1);
            }
        }
        if (kt < FD / 32 - 1) enc_sts(sA[buf ^ 1], sB[buf ^ 1], tid, ra, rb);
        __syncthreads();
    }
    const int g = lane >> 2, qd2 = (lane & 3) * 2;
#pragma unroll
    for (int mt = 0; mt < 2; mt++) {
        int r0 = m0 + wm * 32 + mt * 16 + g;
#pragma unroll
        for (int nt = 0; nt < 4; nt++) {
            int c = wn * 32 + nt * 8 + qd2;
            float bx = bias[c], by = bias[c + 1];
            float2 v0 = make_float2(acc[mt][nt][0] + bx, acc[mt][nt][1] + by);
            float2 v1 = make_float2(acc[mt][nt][2] + bx, acc[mt][nt][3] + by);
            *reinterpret_cast<float2*>(&C[r0 * EMB + c]) = v0;
            *reinterpret_cast<float2*>(&C[(r0 + 8) * EMB + c]) = v1;
        }
    }
}

// ---------------- logits GEMM + streaming logsumexp (v4: grid 256, occ 2) --
// grid 256: rowblk = bid>>2 (128 rows), quarter = bid&3 (256 cols -> 4 chunks
// of 64). One wave across the chip at 2 CTAs/SM; per-row LSE stays in-warp.
__global__ __launch_bounds__(256, 2) void logits_kernel(const float* __restrict__ queue) {
    __shared__ __align__(16) __nv_bfloat16 sB[128][72];   // 144B row stride, 18.4KB
    const int tid = threadIdx.x, lane = tid & 31, w = tid >> 5;
    const int m0 = (blockIdx.x >> 2) * 128, n0 = (blockIdx.x & 3) * 256;
    unsigned base0 = (unsigned)__cvta_generic_to_shared(&sB[0][0]);

    // extract A fragments in two passes through sB (k-cols 0:64 then 64:128)
    unsigned af[8][4];
#pragma unroll
    for (int s = 0; s < 2; s++) {
        if (s == 1) __syncthreads();
#pragma unroll
        for (int it = 0; it < 8; it++) {
            int lin = it * 256 + tid;
            int row = lin >> 4, c4 = (lin & 15) * 4;
            float4 v = *reinterpret_cast<const float4*>(g_q + (m0 + row) * EMB + s * 64 + c4);
            *reinterpret_cast<uint2*>(&sB[row][c4]) = f4bf(v);
        }
        __syncthreads();
#pragma unroll
        for (int k = 0; k < 4; k++) {
            int row = w * 16 + (lane & 15);
            int col = k * 16 + (lane >> 4) * 8;
            ldsm4(af[s * 4 + k][0], af[s * 4 + k][1], af[s * 4 + k][2], af[s * 4 + k][3],
                  base0 + (unsigned)(row * 72 + col) * 2u);
        }
    }

    float m0r = -1e30f, m1r = -1e30f, l0r = 0.f, l1r = 0.f;
    for (int ch = 0; ch < 4; ch++) {
        __syncthreads();   // all reads of sB done (af for ch=0, bfr for ch>0)
#pragma unroll
        for (int it = 0; it < 8; it++) {
            int lin = it * 256 + tid;
            float4 v = *reinterpret_cast<const float4*>(
                queue + (lin >> 4) * QN + n0 + ch * 64 + (lin & 15) * 4);
            *reinterpret_cast<uint2*>(&sB[lin >> 4][(lin & 15) * 4]) = f4bf(v);
        }
        __syncthreads();
        float acc[8][4];
#pragma unroll
        for (int nt = 0; nt < 8; nt++) { acc[nt][0] = acc[nt][1] = acc[nt][2] = acc[nt][3] = 0.f; }
#pragma unroll
        for (int ks = 0; ks < 8; ks++) {
            unsigned bfr[4][4];
#pragma unroll
            for (int p = 0; p < 4; p++) {
                int qd = lane >> 3;
                int row = ks * 16 + (qd & 1) * 8 + (lane & 7);
                int col = p * 16 + (qd >> 1) * 8;
                ldsm4t(bfr[p][0], bfr[p][1], bfr[p][2], bfr[p][3],
                       base0 + (unsigned)(row * 72 + col) * 2u);
            }
#pragma unroll
            for (int nt = 0; nt < 8; nt++)
                mma16816(acc[nt], af[ks], bfr[nt >> 1][(nt & 1) * 2], bfr[nt >> 1][(nt & 1) * 2 + 1]);
        }
        float c0 = -1e30f, c1 = -1e30f;
#pragma unroll
        for (int nt = 0; nt < 8; nt++) {
            c0 = fmaxf(c0, fmaxf(acc[nt][0], acc[nt][1]));
            c1 = fmaxf(c1, fmaxf(acc[nt][2], acc[nt][3]));
        }
        c0 = fmaxf(c0, __shfl_xor_sync(0xffffffffu, c0, 1));
        c0 = fmaxf(c0, __shfl_xor_sync(0xffffffffu, c0, 2));
        c1 = fmaxf(c1, __shfl_xor_sync(0xffffffffu, c1, 1));
        c1 = fmaxf(c1, __shfl_xor_sync(0xffffffffu, c1, 2));
        float n0m = fmaxf(m0r, c0), n1m = fmaxf(m1r, c1);
        float s0 = 0.f, s1 = 0.f;
#pragma unroll
        for (int nt = 0; nt < 8; nt++) {
            s0 += __expf(acc[nt][0] - n0m) + __expf(acc[nt][1] - n0m);
            s1 += __expf(acc[nt][2] - n1m) + __expf(acc[nt][3] - n1m);
        }
        s0 += __shfl_xor_sync(0xffffffffu, s0, 1);
        s0 += __shfl_xor_sync(0xffffffffu, s0, 2);
        s1 += __shfl_xor_sync(0xffffffffu, s1, 1);
        s1 += __shfl_xor_sync(0xffffffffu, s1, 2);
        l0r = l0r * __expf(m0r - n0m) + s0; m0r = n0m;
        l1r = l1r * __expf(m1r - n1m) + s1; m1r = n1m;
    }
    if ((lane & 3) == 0) {
        int q = blockIdx.x & 3;
        int r = m0 + w * 16 + (lane >> 2);
        g_m[q * NW + r] = m0r;      g_l[q * NW + r] = l0r;
        g_m[q * NW + r + 8] = m1r;  g_l[q * NW + r + 8] = l1r;
    }
}

// ---------------- per-row CE v2 (4-quarter merge) + fused final ------------
// grid 256 x 8 warps, 4 rows per warp: lane j loads float4 j of q-row and k-row.
__global__ void row_ce_kernel(const int* __restrict__ wlab, float* __restrict__ out) {
    const int tid = threadIdx.x, lane = tid & 31, wid = tid >> 5;
    __shared__ float rs[8], rc[8];
    __shared__ int slast;
    float aS = 0.f, cS = 0.f;

#pragma unroll
    for (int r = 0; r < 4; r++) {
        const int i = blockIdx.x * 32 + wid * 4 + r;
        // idx computation (uniform across warp; broadcast loads)
        int c = wlab[i];
        int inrange = (c >= 0 && c < NC) ? 1 : 0;
        int cc = inrange ? c : 0;
        int cnt = g_histS[cc];
        int valid = (inrange && cnt > 0) ? 1 : 0;
        int sel = g_rank[i] % (cnt > 0 ? cnt : 1);
        if (sel >= POSCAP || sel < 0) sel = 0;
        int idx = valid ? g_posS[cc * POSCAP + sel] : 0;

        // coalesced per-row dot: lane j covers elements 4j..4j+3
        float4 a = *reinterpret_cast<const float4*>(g_q + i * EMB + lane * 4);
        float4 b = *reinterpret_cast<const float4*>(g_k + idx * EMB + lane * 4);
        float s = a.x * b.x + a.y * b.y + a.z * b.z + a.w * b.w;
#pragma unroll
        for (int o = 16; o; o >>= 1) s += __shfl_xor_sync(0xffffffffu, s, o);

        // merge 4 quarter-lse states (fixed order: 0,1,2,3)
        float M = g_m[i], L = g_l[i];
#pragma unroll
        for (int h = 1; h < 4; h++) {
            float mh = g_m[h * NW + i], lh = g_l[h * NW + i];
            float Mn = fmaxf(M, mh);
            L = L * __expf(M - Mn) + lh * __expf(mh - Mn);
            M = Mn;
        }
        float lpos = s;
        float Mf = fmaxf(M, lpos);
        float Lf = L * __expf(M - Mf) + __expf(lpos - Mf);
        float ce = Mf + logf(Lf) - lpos;
        if (lane == 0) { aS += ce * (valid ? 1.f : 0.f); cS += valid ? 1.f : 0.f; }
    }
    if (lane == 0) { rs[wid] = aS; rc[wid] = cS; }
    __syncthreads();
    if (tid == 0) {
        float A = 0.f, C = 0.f;
#pragma unroll
        for (int ww = 0; ww < 8; ww++) { A += rs[ww]; C += rc[ww]; }
        g_psum[blockIdx.x] = A;
        g_pcnt[blockIdx.x] = C;
        __threadfence();
        unsigned t = atomicAdd(&g_ticket, 1u);
        slast = (t == 255u) ? 1 : 0;
    }
    __syncthreads();
    // last block: deterministic fixed-tree reduction over 256 partials
    if (slast) {
        float s2 = g_psum[tid], c2 = g_pcnt[tid];
#pragma unroll
        for (int o = 16; o; o >>= 1) {
            s2 += __shfl_xor_sync(0xffffffffu, s2, o);
            c2 += __shfl_xor_sync(0xffffffffu, c2, o);
        }
        __syncthreads();   // rs/rc reuse
        if (lane == 0) { rs[wid] = s2; rc[wid] = c2; }
        __syncthreads();
        if (tid == 0) {
            float S = 0.f, Cn = 0.f;
#pragma unroll
            for (int ww = 0; ww < 8; ww++) { S += rs[ww]; Cn += rc[ww]; }
            out[0] = S / fmaxf(Cn, 1.f);
        }
    }
}

// ---------------- launch ----------------
extern "C" void kernel_launch(void* const* d_in, const int* in_sizes, int n_in,
                              void* d_out, int out_size) {
    const float* fs    = (const float*)d_in[0];   // feats_strong [8192,1024]
    const float* fw    = (const float*)d_in[1];   // feats_weak   [8192,1024]
    const int*   slab  = (const int*)d_in[2];     // strong_labels (int32)
    const int*   wlab  = (const int*)d_in[3];     // weak_labels   (int32)
    const float* Wq    = (const float*)d_in[4];
    const float* bq    = (const float*)d_in[5];
    const float* Wk    = (const float*)d_in[6];
    const float* bk    = (const float*)d_in[7];
    const float* queue = (const float*)d_in[8];   // [1024,128] flat
    float* out = (float*)d_out;

    label_scan_kernel<<<2 * NC, 256>>>(slab, wlab);
    encoder_gemm_kernel<<<256, 256>>>(fw, fs, Wq, bq, Wk, bk);
    logits_kernel<<<256, 256>>>(queue);
    row_ce_kernel<<<256, 256>>>(wlab, out);
}

// round 17
// speedup vs baseline: 1.3928x; 1.3560x over previous
#include <cuda_runtime.h>
#include <cuda_bf16.h>

#define NW 8192
#define NS 8192
#define FD 1024
#define EMB 128
#define QN 1024
#define NC 80
#define POSCAP 512

// ---------------- scratch (device globals; no allocation) ----------------
__device__ float g_q[NW * EMB];
__device__ float g_k[NS * EMB];
__device__ int   g_rank[NW];
__device__ int   g_posS[NC * POSCAP];
__device__ int   g_histS[NC];
__device__ float g_m[2 * NW];
__device__ float g_l[2 * NW];
__device__ float g_psum[256];
__device__ float g_pcnt[256];
__device__ unsigned g_ticket;
__device__ __align__(16) __nv_bfloat16 g_Wt[2][128 * 1024]; // W^T bf16 [n][k]
__device__ __align__(16) __nv_bfloat16 g_Qt[1024 * 128];    // queue^T bf16 [j][e]

// ---------------- helpers ----------------
__device__ __forceinline__ uint2 f4bf(float4 v) {
    __nv_bfloat162 lo = __floats2bfloat162_rn(v.x, v.y);
    __nv_bfloat162 hi = __floats2bfloat162_rn(v.z, v.w);
    uint2 r;
    r.x = *reinterpret_cast<unsigned int*>(&lo);
    r.y = *reinterpret_cast<unsigned int*>(&hi);
    return r;
}
__device__ __forceinline__ void ldsm4(unsigned &r0, unsigned &r1, unsigned &r2, unsigned &r3, unsigned addr) {
    asm volatile("ldmatrix.sync.aligned.m8n8.x4.shared.b16 {%0,%1,%2,%3}, [%4];"
                 : "=r"(r0), "=r"(r1), "=r"(r2), "=r"(r3) : "r"(addr));
}
__device__ __forceinline__ void mma16816(float* c, const unsigned* a, unsigned b0, unsigned b1) {
    asm volatile("mma.sync.aligned.m16n8k16.row.col.f32.bf16.bf16.f32 "
                 "{%0,%1,%2,%3}, {%4,%5,%6,%7}, {%8,%9}, {%0,%1,%2,%3};"
                 : "+f"(c[0]), "+f"(c[1]), "+f"(c[2]), "+f"(c[3])
                 : "r"(a[0]), "r"(a[1]), "r"(a[2]), "r"(a[3]), "r"(b0), "r"(b1));
}

// ---------------- label logic (v3, proven) ----------------
__global__ void label_scan_kernel(const int* __restrict__ slab,
                                  const int* __restrict__ wlab) {
    const int b = blockIdx.x;
    const bool strong = b < NC;
    const int c = strong ? b : b - NC;
    const int* lab = strong ? slab : wlab;
    __shared__ int sl[NS];
    __shared__ int wsum[8];
    const int tid = threadIdx.x, lane = tid & 31, wid = tid >> 5;
    if (b == 0 && tid == 0) g_ticket = 0;
#pragma unroll
    for (int it = 0; it < 8; it++) {
        int lin = it * 256 + tid;
        int4 v = reinterpret_cast<const int4*>(lab)[lin];
        *reinterpret_cast<int4*>(&sl[lin * 4]) = v;
    }
    __syncthreads();
    const int base = tid * 32;
    int cnt = 0;
#pragma unroll
    for (int j = 0; j < 32; j++) cnt += (sl[base + j] == c) ? 1 : 0;
    int x = cnt;
#pragma unroll
    for (int o = 1; o < 32; o <<= 1) {
        int y = __shfl_up_sync(0xffffffffu, x, o);
        if (lane >= o) x += y;
    }
    if (lane == 31) wsum[wid] = x;
    __syncthreads();
    int wpre = 0, tot = 0;
#pragma unroll
    for (int ww = 0; ww < 8; ww++) {
        if (ww < wid) wpre += wsum[ww];
        tot += wsum[ww];
    }
    int pos = wpre + x - cnt;
#pragma unroll
    for (int j = 0; j < 32; j++) {
        int jj = base + j;
        if (sl[jj] == c) {
            if (strong) { if (pos < POSCAP) g_posS[c * POSCAP + pos] = jj; }
            else g_rank[jj] = pos;
            pos++;
        }
    }
    if (strong && tid == 0) g_histS[c] = tot;
}

// ---------------- prep: transpose Wq/Wk/queue to K-major bf16 --------------
__global__ __launch_bounds__(256, 1) void prep_transpose(
    const float* __restrict__ Wq, const float* __restrict__ Wk,
    const float* __restrict__ queue) {
    __shared__ float t[64][68];
    const int bid = blockIdx.x, tid = threadIdx.x;
    const float* src;
    __nv_bfloat16* dst;
    int R, C, tile;
    if (bid < 32)      { src = Wq;    dst = g_Wt[0]; R = 1024; C = 128;  tile = bid; }
    else if (bid < 64) { src = Wk;    dst = g_Wt[1]; R = 1024; C = 128;  tile = bid - 32; }
    else               { src = queue; dst = g_Qt;    R = 128;  C = 1024; tile = bid - 64; }
    const int tilesC = C / 64;
    const int r0 = (tile / tilesC) * 64, c0 = (tile % tilesC) * 64;
#pragma unroll
    for (int it = 0; it < 4; it++) {
        int lin = it * 256 + tid;
        int rr = lin >> 4, c4 = lin & 15;
        float4 v = *reinterpret_cast<const float4*>(src + (size_t)(r0 + rr) * C + c0 + c4 * 4);
        *reinterpret_cast<float4*>(&t[rr][c4 * 4]) = v;
    }
    __syncthreads();
#pragma unroll
    for (int it = 0; it < 4; it++) {
        int lin = it * 256 + tid;
        int n = lin >> 4, kq = lin & 15;
        float4 v = make_float4(t[kq * 4 + 0][n], t[kq * 4 + 1][n],
                               t[kq * 4 + 2][n], t[kq * 4 + 3][n]);
        uint2 p = f4bf(v);
        *reinterpret_cast<uint2*>(dst + (size_t)(c0 + n) * R + r0 + kq * 4) = p;
    }
}

// ---------------- encoder GEMM (BM=64, 2 CTAs/SM, bf16 K-major B) ----------
// blocks [0,128): q ; [128,256): k. BK=32, 8 warps (2x4), single-sync dbuf.
__global__ __launch_bounds__(256, 2) void encoder_gemm_kernel(
    const float* __restrict__ fw, const float* __restrict__ fs,
    const float* __restrict__ bq, const float* __restrict__ bk) {
    __shared__ __align__(16) __nv_bfloat16 sA[2][64][40];    // A [m][k], 80B rows
    __shared__ __align__(16) __nv_bfloat16 sB[2][128][40];   // B [n][k], 80B rows
    const int tid = threadIdx.x, lane = tid & 31, wid = tid >> 5;
    const int wm = wid >> 2, wn = wid & 3;
    const int qd = lane >> 3;
    const float *A, *bias;
    const __nv_bfloat16* Wt;
    float* C;
    if (blockIdx.x < 128) { A = fw; Wt = g_Wt[0]; bias = bq; C = g_q; }
    else                  { A = fs; Wt = g_Wt[1]; bias = bk; C = g_k; }
    const int m0 = (blockIdx.x & 127) * 64;

    float acc[2][4][4];
#pragma unroll
    for (int mt = 0; mt < 2; mt++)
#pragma unroll
        for (int nt = 0; nt < 4; nt++)
#pragma unroll
            for (int j = 0; j < 4; j++) acc[mt][nt][j] = 0.f;

    float4 ra[2];
    uint4 rbv[2];
    // stage 0
#pragma unroll
    for (int it = 0; it < 2; it++) {
        int lin = it * 256 + tid;
        ra[it] = *reinterpret_cast<const float4*>(A + (size_t)(m0 + (lin >> 3)) * FD + (lin & 7) * 4);
        rbv[it] = *reinterpret_cast<const uint4*>(Wt + (size_t)(lin >> 2) * FD + (lin & 3) * 8);
    }
#pragma unroll
    for (int it = 0; it < 2; it++) {
        int lin = it * 256 + tid;
        *reinterpret_cast<uint2*>(&sA[0][lin >> 3][(lin & 7) * 4]) = f4bf(ra[it]);
        *reinterpret_cast<uint4*>(&sB[0][lin >> 2][(lin & 3) * 8]) = rbv[it];
    }
    __syncthreads();

    for (int kt = 0; kt < FD / 32; kt++) {
        const int buf = kt & 1;
        if (kt < FD / 32 - 1) {
#pragma unroll
            for (int it = 0; it < 2; it++) {
                int lin = it * 256 + tid;
                ra[it] = *reinterpret_cast<const float4*>(
                    A + (size_t)(m0 + (lin >> 3)) * FD + (kt + 1) * 32 + (lin & 7) * 4);
                rbv[it] = *reinterpret_cast<const uint4*>(
                    Wt + (size_t)(lin >> 2) * FD + (kt + 1) * 32 + (lin & 3) * 8);
            }
        }
        unsigned abase = (unsigned)__cvta_generic_to_shared(&sA[buf][0][0]);
        unsigned bbase = (unsigned)__cvta_generic_to_shared(&sB[buf][0][0]);
#pragma unroll
        for (int ks = 0; ks < 2; ks++) {
            unsigned af[2][4], bfr[2][4];
#pragma unroll
            for (int mt = 0; mt < 2; mt++) {
                int row = wm * 32 + mt * 16 + (lane & 15);
                ldsm4(af[mt][0], af[mt][1], af[mt][2], af[mt][3],
                      abase + (unsigned)(row * 80 + ks * 32 + (lane >> 4) * 16));
            }
#pragma unroll
            for (int p = 0; p < 2; p++) {
                int row = wn * 32 + p * 16 + (qd & 1) * 8 + (lane & 7);
                ldsm4(bfr[p][0], bfr[p][1], bfr[p][2], bfr[p][3],
                      bbase + (unsigned)(row * 80 + ks * 32 + (qd >> 1) * 16));
            }
#pragma unroll
            for (int nt = 0; nt < 4; nt++) {
                unsigned b0 = bfr[nt >> 1][nt & 1], b1 = bfr[nt >> 1][(nt & 1) + 2];
                mma16816(acc[0][nt], af[0], b0, b1);
                mma16816(acc[1][nt], af[1], b0, b1);
            }
        }
        if (kt < FD / 32 - 1) {
#pragma unroll
            for (int it = 0; it < 2; it++) {
                int lin = it * 256 + tid;
                *reinterpret_cast<uint2*>(&sA[buf ^ 1][lin >> 3][(lin & 7) * 4]) = f4bf(ra[it]);
                *reinterpret_cast<uint4*>(&sB[buf ^ 1][lin >> 2][(lin & 3) * 8]) = rbv[it];
            }
        }
        __syncthreads();
    }
    const int g = lane >> 2, qd2 = (lane & 3) * 2;
#pragma unroll
    for (int mt = 0; mt < 2; mt++) {
        int r0 = m0 + wm * 32 + mt * 16 + g;
#pragma unroll
        for (int nt = 0; nt < 4; nt++) {
            int c = wn * 32 + nt * 8 + qd2;
            float bx = bias[c], by = bias[c + 1];
            float2 v0 = make_float2(acc[mt][nt][0] + bx, acc[mt][nt][1] + by);
            float2 v1 = make_float2(acc[mt][nt][2] + bx, acc[mt][nt][3] + by);
            *reinterpret_cast<float2*>(&C[(size_t)r0 * EMB + c]) = v0;
            *reinterpret_cast<float2*>(&C[(size_t)(r0 + 8) * EMB + c]) = v1;
        }
    }
}

// ---------------- logits GEMM + streaming LSE (bf16 K-major B) -------------
// grid 128: rowblk = bid>>1 (128 rows), half = bid&1 (512 cols, 8 chunks of 64).
// One 128x136 buffer: A extracted in place, then row-halves ping-pong B chunks.
__global__ __launch_bounds__(256, 1) void logits_kernel() {
    __shared__ __align__(16) __nv_bfloat16 sT[128][136];  // 272B rows
    const int tid = threadIdx.x, lane = tid & 31, w = tid >> 5;
    const int qd = lane >> 3;
    const int m0 = (blockIdx.x >> 1) * 128, n0 = (blockIdx.x & 1) * 512;
    unsigned base = (unsigned)__cvta_generic_to_shared(&sT[0][0]);

    // stage q [128 m][128 k] fp32 -> bf16
#pragma unroll
    for (int it = 0; it < 16; it++) {
        int lin = it * 256 + tid;
        int row = lin >> 5, c4 = lin & 31;
        float4 v = *reinterpret_cast<const float4*>(g_q + (size_t)(m0 + row) * EMB + c4 * 4);
        *reinterpret_cast<uint2*>(&sT[row][c4 * 4]) = f4bf(v);
    }
    __syncthreads();
    unsigned af[8][4];
#pragma unroll
    for (int ks = 0; ks < 8; ks++) {
        int row = w * 16 + (lane & 15);
        ldsm4(af[ks][0], af[ks][1], af[ks][2], af[ks][3],
              base + (unsigned)(row * 272 + ks * 32 + (lane >> 4) * 16));
    }
    __syncthreads();   // A reads done before B overwrites

    // preload chunk 0 into rows [0,64)
    uint4 rq[4];
#pragma unroll
    for (int it = 0; it < 4; it++) {
        int lin = it * 256 + tid;
        rq[it] = *reinterpret_cast<const uint4*>(g_Qt + (size_t)(n0 + (lin >> 4)) * 128 + (lin & 15) * 8);
    }
#pragma unroll
    for (int it = 0; it < 4; it++) {
        int lin = it * 256 + tid;
        *reinterpret_cast<uint4*>(&sT[lin >> 4][(lin & 15) * 8]) = rq[it];
    }
    __syncthreads();

    float m0r = -1e30f, m1r = -1e30f, l0r = 0.f, l1r = 0.f;
    for (int ch = 0; ch < 8; ch++) {
        const int rb = (ch & 1) * 64;          // this chunk's row half
        if (ch < 7) {
#pragma unroll
            for (int it = 0; it < 4; it++) {
                int lin = it * 256 + tid;
                rq[it] = *reinterpret_cast<const uint4*>(
                    g_Qt + (size_t)(n0 + (ch + 1) * 64 + (lin >> 4)) * 128 + (lin & 15) * 8);
            }
        }
        float acc[8][4];
#pragma unroll
        for (int nt = 0; nt < 8; nt++) { acc[nt][0] = acc[nt][1] = acc[nt][2] = acc[nt][3] = 0.f; }
#pragma unroll
        for (int ks = 0; ks < 8; ks++) {
            unsigned bfr[4][4];
#pragma unroll
            for (int p = 0; p < 4; p++) {
                int row = rb + p * 16 + (qd & 1) * 8 + (lane & 7);
                ldsm4(bfr[p][0], bfr[p][1], bfr[p][2], bfr[p][3],
                      base + (unsigned)(row * 272 + ks * 32 + (qd >> 1) * 16));
            }
#pragma unroll
            for (int nt = 0; nt < 8; nt++)
                mma16816(acc[nt], af[ks], bfr[nt >> 1][nt & 1], bfr[nt >> 1][(nt & 1) + 2]);
        }
        // online logsumexp (rows g=lane>>2 and g+8 of warp band)
        float c0 = -1e30f, c1 = -1e30f;
#pragma unroll
        for (int nt = 0; nt < 8; nt++) {
            c0 = fmaxf(c0, fmaxf(acc[nt][0], acc[nt][1]));
            c1 = fmaxf(c1, fmaxf(acc[nt][2], acc[nt][3]));
        }
        c0 = fmaxf(c0, __shfl_xor_sync(0xffffffffu, c0, 1));
        c0 = fmaxf(c0, __shfl_xor_sync(0xffffffffu, c0, 2));
        c1 = fmaxf(c1, __shfl_xor_sync(0xffffffffu, c1, 1));
        c1 = fmaxf(c1, __shfl_xor_sync(0xffffffffu, c1, 2));
        float n0m = fmaxf(m0r, c0), n1m = fmaxf(m1r, c1);
        float s0 = 0.f, s1 = 0.f;
#pragma unroll
        for (int nt = 0; nt < 8; nt++) {
            s0 += __expf(acc[nt][0] - n0m) + __expf(acc[nt][1] - n0m);
            s1 += __expf(acc[nt][2] - n1m) + __expf(acc[nt][3] - n1m);
        }
        s0 += __shfl_xor_sync(0xffffffffu, s0, 1);
        s0 += __shfl_xor_sync(0xffffffffu, s0, 2);
        s1 += __shfl_xor_sync(0xffffffffu, s1, 1);
        s1 += __shfl_xor_sync(0xffffffffu, s1, 2);
        l0r = l0r * __expf(m0r - n0m) + s0; m0r = n0m;
        l1r = l1r * __expf(m1r - n1m) + s1; m1r = n1m;
        if (ch < 7) {   // store next chunk into the other row-half
            int ob = (rb ^ 64);
#pragma unroll
            for (int it = 0; it < 4; it++) {
                int lin = it * 256 + tid;
                *reinterpret_cast<uint4*>(&sT[ob + (lin >> 4)][(lin & 15) * 8]) = rq[it];
            }
        }
        __syncthreads();
    }
    if ((lane & 3) == 0) {
        int half = blockIdx.x & 1;
        int r = m0 + w * 16 + (lane >> 2);
        g_m[half * NW + r] = m0r;      g_l[half * NW + r] = l0r;
        g_m[half * NW + r + 8] = m1r;  g_l[half * NW + r + 8] = l1r;
    }
}

// ---------------- per-row CE v2 (R13-proven) + fused final -----------------
__global__ void row_ce_kernel(const int* __restrict__ wlab, float* __restrict__ out) {
    const int tid = threadIdx.x, lane = tid & 31, wid = tid >> 5;
    __shared__ float rs[8], rc[8];
    __shared__ int slast;
    float aS = 0.f, cS = 0.f;
#pragma unroll
    for (int r = 0; r < 4; r++) {
        const int i = blockIdx.x * 32 + wid * 4 + r;
        int c = wlab[i];
        int inrange = (c >= 0 && c < NC) ? 1 : 0;
        int cc = inrange ? c : 0;
        int cnt = g_histS[cc];
        int valid = (inrange && cnt > 0) ? 1 : 0;
        int sel = g_rank[i] % (cnt > 0 ? cnt : 1);
        if (sel >= POSCAP || sel < 0) sel = 0;
        int idx = valid ? g_posS[cc * POSCAP + sel] : 0;

        float4 a = *reinterpret_cast<const float4*>(g_q + (size_t)i * EMB + lane * 4);
        float4 b = *reinterpret_cast<const float4*>(g_k + (size_t)idx * EMB + lane * 4);
        float s = a.x * b.x + a.y * b.y + a.z * b.z + a.w * b.w;
#pragma unroll
        for (int o = 16; o; o >>= 1) s += __shfl_xor_sync(0xffffffffu, s, o);

        float ma = g_m[i], la = g_l[i], mb = g_m[NW + i], lb = g_l[NW + i];
        float M = fmaxf(ma, mb);
        float L = la * __expf(ma - M) + lb * __expf(mb - M);
        float lpos = s;
        float Mf = fmaxf(M, lpos);
        float Lf = L * __expf(M - Mf) + __expf(lpos - Mf);
        float ce = Mf + logf(Lf) - lpos;
        if (lane == 0) { aS += ce * (valid ? 1.f : 0.f); cS += valid ? 1.f : 0.f; }
    }
    if (lane == 0) { rs[wid] = aS; rc[wid] = cS; }
    __syncthreads();
    if (tid == 0) {
        float A = 0.f, C = 0.f;
#pragma unroll
        for (int ww = 0; ww < 8; ww++) { A += rs[ww]; C += rc[ww]; }
        g_psum[blockIdx.x] = A;
        g_pcnt[blockIdx.x] = C;
        __threadfence();
        unsigned t = atomicAdd(&g_ticket, 1u);
        slast = (t == 255u) ? 1 : 0;
    }
    __syncthreads();
    if (slast) {
        float s2 = g_psum[tid], c2 = g_pcnt[tid];
#pragma unroll
        for (int o = 16; o; o >>= 1) {
            s2 += __shfl_xor_sync(0xffffffffu, s2, o);
            c2 += __shfl_xor_sync(0xffffffffu, c2, o);
        }
        __syncthreads();
        if (lane == 0) { rs[wid] = s2; rc[wid] = c2; }
        __syncthreads();
        if (tid == 0) {
            float S = 0.f, Cn = 0.f;
#pragma unroll
            for (int ww = 0; ww < 8; ww++) { S += rs[ww]; Cn += rc[ww]; }
            out[0] = S / fmaxf(Cn, 1.f);
        }
    }
}

// ---------------- launch ----------------
extern "C" void kernel_launch(void* const* d_in, const int* in_sizes, int n_in,
                              void* d_out, int out_size) {
    const float* fs    = (const float*)d_in[0];
    const float* fw    = (const float*)d_in[1];
    const int*   slab  = (const int*)d_in[2];
    const int*   wlab  = (const int*)d_in[3];
    const float* Wq    = (const float*)d_in[4];
    const float* bq    = (const float*)d_in[5];
    const float* Wk    = (const float*)d_in[6];
    const float* bk    = (const float*)d_in[7];
    const float* queue = (const float*)d_in[8];
    float* out = (float*)d_out;

    label_scan_kernel<<<2 * NC, 256>>>(slab, wlab);
    prep_transpose<<<96, 256>>>(Wq, Wk, queue);
    encoder_gemm_kernel<<<256, 256>>>(fw, fs, bq, bk);
    logits_kernel<<<128, 256>>>();
    row_ce_kernel<<<256, 256>>>(wlab, out);
}